// round 16
// baseline (speedup 1.0000x reference)
#include <cuda_runtime.h>
#include <cuda_fp16.h>
#include <cstdint>

#define MARGIN 0.3f
#define DIM  128
#define TILE 128
#define MAXN 4096
#define MAXT (MAXN / TILE)
#define MAXPAIR (MAXT * (MAXT + 1) / 2)
#define CT   16384                 // image chunk tile: 128 rows x 64 fp16 cols (SW128)

// ---- dynamic smem layout (bytes) ----
#define SM_CBI   0                 // 128 f
#define SM_CBJ   512
#define SM_N1BI  1024
#define SM_N1BJ  1536
#define SM_N2BI  2048
#define SM_N2BJ  2560
#define SM_RMI   3072              // 128 u
#define SM_RMJ   3584              // 128 u
#define SM_SSUM  4096              // 8 f
#define SM_OPS   8192              // 96KB operand region, 1024-aligned
#define SMEM_TOTAL (SM_OPS + 96 * 1024)

// operands (hi-only fp16, 2-chunk full-K tiles of 32K each):
// A [0,32K) = p1bi; B1 [32K,64K) = p1bj; B2 [64K,96K) = p2bj
// phase2 (off-diag): p2bi reloaded into A region; B1 reused as B.
#define P_A  0
#define P_B1 (32 * 1024)
#define P_B2 (64 * 1024)

__device__ float g_n1[MAXN], g_n2[MAXN], g_C[MAXN];
__device__ unsigned int g_rowmax[MAXN];      // zero at load; finalizer re-zeros
__device__ float g_partial[MAXPAIR];
__device__ unsigned int g_work;              // work ticket; finalizer re-zeros
__device__ unsigned int g_done;              // CTA done counter; finalizer re-zeros

// pre-swizzled fp16 hi images: [tile][chunk][16KB]
__device__ __align__(16) unsigned char g_img_p1h[MAXT * 2 * CT];
__device__ __align__(16) unsigned char g_img_p2h[MAXT * 2 * CT];

__device__ __forceinline__ uint32_t smem_u32(const void* p) {
    uint32_t a;
    asm("{ .reg .u64 t; cvta.to.shared.u64 t, %1; cvt.u32.u64 %0, t; }" : "=r"(a) : "l"(p));
    return a;
}
__device__ __forceinline__ int swz(int row, int kc) {
    int b = row * 128 + kc * 2;
    return b ^ ((b >> 3) & 0x70);
}
__device__ __forceinline__ uint32_t taddrA(uint32_t base0, int row, int kcol) {
    return base0 + ((kcol >> 6) << 14) + swz(row, kcol & 63);
}
__device__ __forceinline__ void ldsm4(uint32_t addr, uint32_t r[4]) {
    asm volatile("ldmatrix.sync.aligned.m8n8.x4.shared.b16 {%0,%1,%2,%3}, [%4];"
                 : "=r"(r[0]), "=r"(r[1]), "=r"(r[2]), "=r"(r[3]) : "r"(addr));
}
__device__ __forceinline__ void cp16(uint32_t saddr, const void* g) {
    asm volatile("cp.async.cg.shared.global [%0], [%1], 16;" :: "r"(saddr), "l"(g));
}
#define CP_COMMIT() asm volatile("cp.async.commit_group;" ::: "memory")
#define CP_WAIT0()  asm volatile("cp.async.wait_group 0;" ::: "memory")
#define CP_WAIT1()  asm volatile("cp.async.wait_group 1;" ::: "memory")

#define MMA(d, a, b)                                                               \
    asm volatile("mma.sync.aligned.m16n8k16.row.col.f32.f16.f16.f32 "              \
                 "{%0,%1,%2,%3},{%4,%5,%6,%7},{%8,%9},{%0,%1,%2,%3};"              \
                 : "+f"((d)[0]), "+f"((d)[1]), "+f"((d)[2]), "+f"((d)[3])          \
                 : "r"((a)[0]), "r"((a)[1]), "r"((a)[2]), "r"((a)[3]),             \
                   "r"((b)[0]), "r"((b)[1]))

union HU { __half2 h; uint32_t u; };

__device__ __forceinline__ void cpa(uint32_t sdst, const unsigned char* gsrc, int bytes, int tid) {
    for (int t = tid * 16; t < bytes; t += 4096) cp16(sdst + t, gsrc + t);
}

__device__ __forceinline__ void decode(int w, int nt, int& bi, int& bj) {
    bi = 0;
    int rem = w;
    while (rem >= nt - bi) { rem -= (nt - bi); bi++; }
    bj = bi + rem;
}

// item prologue: g0 = A (p1bi, 32K) + B1 (p1bj, 32K); g1 = B2 (p2bj, 32K)
__device__ __forceinline__ void load_item(uint32_t OPS, int bi, int bj, int tid) {
    cpa(OPS + P_A,  g_img_p1h + (size_t)(bi * 2) * CT, 2 * CT, tid);
    cpa(OPS + P_B1, g_img_p1h + (size_t)(bj * 2) * CT, 2 * CT, tid);
    CP_COMMIT();                                                   // g0
    cpa(OPS + P_B2, g_img_p2h + (size_t)(bj * 2) * CT, 2 * CT, tid);
    CP_COMMIT();                                                   // g1
}

// full-K gram (8 ksteps), warp tile 32x64: per kstep 6 ldsm.x4 -> 16 MMA
__device__ __forceinline__ void gram8(
    uint32_t AH, uint32_t BH,
    int arow, int akoff, int brow, int bkoff, float (&acc)[2][8][4])
{
#pragma unroll
    for (int ks = 0; ks < 8; ks++) {
        const int k0 = ks * 16;
        uint32_t ah[2][4];
#pragma unroll
        for (int mf = 0; mf < 2; mf++)
            ldsm4(taddrA(AH, arow + mf * 16, k0 + akoff), ah[mf]);
        uint32_t bh[8][2];
#pragma unroll
        for (int np = 0; np < 4; np++) {
            uint32_t t4[4];
            ldsm4(taddrA(BH, brow + np * 16, k0 + bkoff), t4);
            bh[2*np][0]=t4[0]; bh[2*np][1]=t4[1]; bh[2*np+1][0]=t4[2]; bh[2*np+1][1]=t4[3];
        }
#pragma unroll
        for (int mf = 0; mf < 2; mf++)
#pragma unroll
            for (int nf = 0; nf < 8; nf++)
                MMA(acc[mf][nf], ah[mf], bh[nf]);
    }
}

// rows anchored: C[row] - n[col] + 2*acc
__device__ __forceinline__ void epi_normal(
    float (&acc)[2][8][4], const float* Crow, const float* ncol,
    int wm, int wn, int qr, int qc, int l, bool dz, int rbase, int cbase,
    unsigned int* srm, float& sum)
{
    float Cr[2][2], nc[8][2];
#pragma unroll
    for (int mf = 0; mf < 2; mf++) {
        int r0 = wm * 32 + mf * 16 + qr;
        Cr[mf][0] = Crow[r0]; Cr[mf][1] = Crow[r0 + 8];
    }
#pragma unroll
    for (int nf = 0; nf < 8; nf++) {
        int c0 = wn * 64 + nf * 8 + qc;
        nc[nf][0] = ncol[c0]; nc[nf][1] = ncol[c0 + 1];
    }
    float rmax[2][2] = {{0.f, 0.f}, {0.f, 0.f}};
#pragma unroll
    for (int mf = 0; mf < 2; mf++)
#pragma unroll
        for (int nf = 0; nf < 8; nf++)
#pragma unroll
            for (int e = 0; e < 4; e++) {
                int rr = e >> 1, cc = e & 1;
                float v = fmaxf(Cr[mf][rr] - nc[nf][cc] + 2.f * acc[mf][nf][e], 0.f);
                if (dz) {
                    int rl = rbase + wm * 32 + mf * 16 + qr + rr * 8;
                    int cl = cbase + wn * 64 + nf * 8 + qc + cc;
                    if (rl == cl) v = 0.f;
                }
                sum += v;
                rmax[mf][rr] = fmaxf(rmax[mf][rr], v);
            }
#pragma unroll
    for (int m = 1; m <= 2; m <<= 1)
#pragma unroll
        for (int mf = 0; mf < 2; mf++) {
            rmax[mf][0] = fmaxf(rmax[mf][0], __shfl_xor_sync(0xffffffffu, rmax[mf][0], m));
            rmax[mf][1] = fmaxf(rmax[mf][1], __shfl_xor_sync(0xffffffffu, rmax[mf][1], m));
        }
    if ((l & 3) == 0) {
#pragma unroll
        for (int mf = 0; mf < 2; mf++) {
            atomicMax(&srm[wm * 32 + mf * 16 + qr],     __float_as_uint(rmax[mf][0]));
            atomicMax(&srm[wm * 32 + mf * 16 + qr + 8], __float_as_uint(rmax[mf][1]));
        }
    }
}

// cols anchored: C[col] - n[row] + 2*acc
__device__ __forceinline__ void epi_trans(
    float (&acc)[2][8][4], const float* Ccol, const float* nrow,
    int wm, int wn, int qr, int qc, int l,
    unsigned int* srm, float& sum)
{
    float Ct[8][2], nr[2][2];
#pragma unroll
    for (int nf = 0; nf < 8; nf++) {
        int c0 = wn * 64 + nf * 8 + qc;
        Ct[nf][0] = Ccol[c0]; Ct[nf][1] = Ccol[c0 + 1];
    }
#pragma unroll
    for (int mf = 0; mf < 2; mf++) {
        int r0 = wm * 32 + mf * 16 + qr;
        nr[mf][0] = nrow[r0]; nr[mf][1] = nrow[r0 + 8];
    }
    float cmax[8][2];
#pragma unroll
    for (int nf = 0; nf < 8; nf++) { cmax[nf][0] = 0.f; cmax[nf][1] = 0.f; }
#pragma unroll
    for (int mf = 0; mf < 2; mf++)
#pragma unroll
        for (int nf = 0; nf < 8; nf++)
#pragma unroll
            for (int e = 0; e < 4; e++) {
                int rr = e >> 1, cc = e & 1;
                float v = fmaxf(Ct[nf][cc] - nr[mf][rr] + 2.f * acc[mf][nf][e], 0.f);
                sum += v;
                cmax[nf][cc] = fmaxf(cmax[nf][cc], v);
            }
#pragma unroll
    for (int m = 4; m <= 16; m <<= 1)
#pragma unroll
        for (int nf = 0; nf < 8; nf++) {
            cmax[nf][0] = fmaxf(cmax[nf][0], __shfl_xor_sync(0xffffffffu, cmax[nf][0], m));
            cmax[nf][1] = fmaxf(cmax[nf][1], __shfl_xor_sync(0xffffffffu, cmax[nf][1], m));
        }
    if (l < 4) {
#pragma unroll
        for (int nf = 0; nf < 8; nf++) {
            int c0 = wn * 64 + nf * 8 + qc;
            atomicMax(&srm[c0],     __float_as_uint(cmax[nf][0]));
            atomicMax(&srm[c0 + 1], __float_as_uint(cmax[nf][1]));
        }
    }
}

// ---- prep: norms/C + pre-swizzled fp16 hi images ----
__global__ void __launch_bounds__(256)
prep_kernel(const float* __restrict__ p1, const float* __restrict__ p2, int n) {
    int row = blockIdx.x * 8 + (threadIdx.x >> 5);
    int lane = threadIdx.x & 31;
    if (row >= n) return;
    float4 a = ((const float4*)(p1 + (size_t)row * DIM))[lane];
    float4 b = ((const float4*)(p2 + (size_t)row * DIM))[lane];

    float n1 = a.x*a.x + a.y*a.y + a.z*a.z + a.w*a.w;
    float n2 = b.x*b.x + b.y*b.y + b.z*b.z + b.w*b.w;
    float dx = a.x-b.x, dy = a.y-b.y, dz = a.z-b.z, dw = a.w-b.w;
    float dap = dx*dx + dy*dy + dz*dz + dw*dw;
#pragma unroll
    for (int m = 16; m; m >>= 1) {
        n1 += __shfl_xor_sync(0xffffffffu, n1, m);
        n2 += __shfl_xor_sync(0xffffffffu, n2, m);
        dap += __shfl_xor_sync(0xffffffffu, dap, m);
    }
    if (lane == 0) {
        g_n1[row] = n1; g_n2[row] = n2; g_C[row] = dap - n1 + MARGIN;
    }

    int tile = row >> 7, lr = row & 127;
    int c4 = lane * 4, chunk = c4 >> 6, lc = c4 & 63;
    size_t off = (size_t)(tile * 2 + chunk) * CT + swz(lr, lc);

    HU h0, h1;
    h0.h = __floats2half2_rn(a.x, a.y);
    h1.h = __floats2half2_rn(a.z, a.w);
    *(uint2*)(g_img_p1h + off) = make_uint2(h0.u, h1.u);
    h0.h = __floats2half2_rn(b.x, b.y);
    h1.h = __floats2half2_rn(b.z, b.w);
    *(uint2*)(g_img_p2h + off) = make_uint2(h0.u, h1.u);
}

// ---- main: persistent CTAs @2/SM, full-pair items, 32x64 warp tiles ----
__global__ void __launch_bounds__(256, 2)
triplet_persist_kernel(float* __restrict__ out, int n, int nt, int nwork) {
    extern __shared__ char smem[];
    const uint32_t sbase = smem_u32(smem);
    const int tid = threadIdx.x;
    const int wid = tid >> 5;
    const int l   = tid & 31;

    float* sCbi  = (float*)(smem + SM_CBI);
    float* sCbj  = (float*)(smem + SM_CBJ);
    float* sn1bi = (float*)(smem + SM_N1BI);
    float* sn1bj = (float*)(smem + SM_N1BJ);
    float* sn2bi = (float*)(smem + SM_N2BI);
    float* sn2bj = (float*)(smem + SM_N2BJ);
    unsigned int* srm_bi = (unsigned int*)(smem + SM_RMI);
    unsigned int* srm_bj = (unsigned int*)(smem + SM_RMJ);
    float* ssum = (float*)(smem + SM_SSUM);
    const uint32_t OPS = sbase + SM_OPS;

    __shared__ int s_w;

    // warp tiling: 4 (M) x 2 (N), warp tile 32x64 on a 128x128 gram
    const int wm = wid & 3;
    const int wn = wid >> 2;
    const int qr = l >> 2;
    const int qc = (l & 3) * 2;
    const int arow = wm * 32 + (l & 7) + ((l >> 3) & 1) * 8;
    const int akoff = (l >> 4) * 8;
    const int brow = wn * 64 + (l & 7) + ((l >> 4) << 3);   // + np*16 inside gram8
    const int bkoff = ((l >> 3) & 1) * 8;

    if (tid == 0) s_w = (int)atomicAdd(&g_work, 1u);
    __syncthreads();
    int w = s_w;
    if (w < nwork) {
        int bi, bj; decode(w, nt, bi, bj);
        load_item(OPS, bi, bj, tid);                    // g0, g1 outstanding
    }

    while (w < nwork) {
        int bi, bj; decode(w, nt, bi, bj);
        const bool diag = (bi == bj);

        __syncthreads();
        if (tid < 128) {
            srm_bi[tid] = 0u;
            sCbi[tid]  = g_C[bi * TILE + tid];
            sn1bi[tid] = g_n1[bi * TILE + tid];
            sn2bi[tid] = g_n2[bi * TILE + tid];
        } else {
            int t = tid - 128;
            srm_bj[t] = 0u;
            sCbj[t]  = g_C[bj * TILE + t];
            sn1bj[t] = g_n1[bj * TILE + t];
            sn2bj[t] = g_n2[bj * TILE + t];
            if (tid == 255) s_w = (int)atomicAdd(&g_work, 1u);   // next ticket
        }

        float sum = 0.f;

        CP_WAIT1();             // g0 (A + B1) ready
        __syncthreads();        // publishes s_w too
        const int wn_next = s_w;

        // ---- acc1 = p1bi . p1bj^T; epilogues cover B2 flight ----
        {
            float acc[2][8][4];
#pragma unroll
            for (int mf = 0; mf < 2; mf++)
#pragma unroll
                for (int nf = 0; nf < 8; nf++)
#pragma unroll
                    for (int e = 0; e < 4; e++) acc[mf][nf][e] = 0.f;
            gram8(OPS + P_A, OPS + P_B1, arow, akoff, brow, bkoff, acc);
            epi_normal(acc, sCbi, sn1bj, wm, wn, qr, qc, l, diag,
                       bi * TILE, bj * TILE, srm_bi, sum);
            if (!diag)
                epi_trans(acc, sCbj, sn1bi, wm, wn, qr, qc, l, srm_bj, sum);
        }

        CP_WAIT0();             // g1 (B2) ready
        __syncthreads();

        // ---- acc2 = p1bi . p2bj^T ----
        {
            float acc[2][8][4];
#pragma unroll
            for (int mf = 0; mf < 2; mf++)
#pragma unroll
                for (int nf = 0; nf < 8; nf++)
#pragma unroll
                    for (int e = 0; e < 4; e++) acc[mf][nf][e] = 0.f;
            gram8(OPS + P_A, OPS + P_B2, arow, akoff, brow, bkoff, acc);
            __syncthreads();    // A-region reads done (B1 stays resident)

            if (diag) {
                if (wn_next < nwork) {
                    int nbi, nbj; decode(wn_next, nt, nbi, nbj);
                    load_item(OPS, nbi, nbj, tid);
                }
                epi_normal(acc, sCbi, sn2bj, wm, wn, qr, qc, l, true,
                           bi * TILE, bj * TILE, srm_bi, sum);
            } else {
                // phase2 operand: p2bi into the freed A region
                cpa(OPS + P_A, g_img_p2h + (size_t)(bi * 2) * CT, 2 * CT, tid);
                CP_COMMIT();
                epi_normal(acc, sCbi, sn2bj, wm, wn, qr, qc, l, false,
                           bi * TILE, bj * TILE, srm_bi, sum);
            }
        }

        // ---- phase2 (off-diag): G2b^T = p2bi . p1bj^T (B1 reused) ----
        if (!diag) {
            float acc[2][8][4];
#pragma unroll
            for (int mf = 0; mf < 2; mf++)
#pragma unroll
                for (int nf = 0; nf < 8; nf++)
#pragma unroll
                    for (int e = 0; e < 4; e++) acc[mf][nf][e] = 0.f;

            CP_WAIT0();         // p2bi ready
            __syncthreads();
            gram8(OPS + P_A, OPS + P_B1, arow, akoff, brow, bkoff, acc);
            __syncthreads();    // all phase2 operand reads done

            if (wn_next < nwork) {
                int nbi, nbj; decode(wn_next, nt, nbi, nbj);
                load_item(OPS, nbi, nbj, tid);
            }
            epi_trans(acc, sCbj, sn2bi, wm, wn, qr, qc, l, srm_bj, sum);
        }

        // ---- publish this item ----
#pragma unroll
        for (int m = 16; m; m >>= 1) sum += __shfl_xor_sync(0xffffffffu, sum, m);
        if (l == 0) ssum[wid] = sum;
        __syncthreads();
        if (tid < 128)
            atomicMax(&g_rowmax[bi * TILE + tid], srm_bi[tid]);
        else if (!diag)
            atomicMax(&g_rowmax[bj * TILE + (tid - 128)], srm_bj[tid - 128]);
        if (tid == 0) {
            float t = 0.f;
#pragma unroll
            for (int ww = 0; ww < 8; ww++) t += ssum[ww];
            g_partial[w] = t;
        }
        w = wn_next;
    }

    // ---- CTA done; last CTA finalizes ----
    __threadfence();
    __shared__ unsigned int s_last;
    if (tid == 0) s_last = (atomicAdd(&g_done, 1u) == (unsigned)(gridDim.x - 1)) ? 1u : 0u;
    __syncthreads();
    if (!s_last) return;
    __threadfence();

    double smax = 0.0, ssumd = 0.0;
    for (int i = tid; i < n; i += 256) {
        smax += (double)__uint_as_float(g_rowmax[i]);
        g_rowmax[i] = 0u;
    }
    for (int i = tid; i < nwork; i += 256) ssumd += (double)g_partial[i];
#pragma unroll
    for (int m = 16; m; m >>= 1) {
        smax  += __shfl_xor_sync(0xffffffffu, smax, m);
        ssumd += __shfl_xor_sync(0xffffffffu, ssumd, m);
    }
    __shared__ double d1[8], d2[8];
    if (l == 0) { d1[wid] = smax; d2[wid] = ssumd; }
    __syncthreads();
    if (tid == 0) {
        double t1 = 0.0, t2 = 0.0;
#pragma unroll
        for (int ww = 0; ww < 8; ww++) { t1 += d1[ww]; t2 += d2[ww]; }
        out[0] = (float)(t1 / (double)n);
        out[1] = (float)(t2 / (2.0 * (double)n * (double)(n - 1)));
        g_work = 0u;
        g_done = 0u;
    }
}

extern "C" void kernel_launch(void* const* d_in, const int* in_sizes, int n_in,
                              void* d_out, int out_size) {
    const float* p1 = (const float*)d_in[0];
    const float* p2 = (const float*)d_in[1];
    float* out = (float*)d_out;
    const int n = in_sizes[0] / DIM;            // 4096
    const int nt = n / TILE;                    // 32
    const int nwork = nt * (nt + 1) / 2;        // 528 full pairs

    int nsm = 148;
    cudaDeviceGetAttribute(&nsm, cudaDevAttrMultiProcessorCount, 0);

    cudaFuncSetAttribute(triplet_persist_kernel,
                         cudaFuncAttributeMaxDynamicSharedMemorySize, SMEM_TOTAL);

    prep_kernel<<<n / 8, 256>>>(p1, p2, n);
    triplet_persist_kernel<<<nsm * 2, 256, SMEM_TOTAL>>>(out, n, nt, nwork);
}

// round 17
// speedup vs baseline: 1.0104x; 1.0104x over previous
#include <cuda_runtime.h>
#include <cuda_fp16.h>
#include <cstdint>

#define MARGIN 0.3f
#define DIM  128
#define TILE 128
#define MAXN 4096
#define MAXT (MAXN / TILE)
#define MAXPAIR (MAXT * (MAXT + 1) / 2)
#define CT   16384                 // image chunk tile: 128 rows x 64 fp16 cols (SW128)

// ---- dynamic smem layout (bytes) ----
#define SM_CBI   0                 // 128 f
#define SM_N1BI  512
#define SM_N2BI  1024
#define SM_CBJH  1536              // 64 f
#define SM_N1BJH 1792
#define SM_N2BJH 2048
#define SM_RMI   2304              // 128 u
#define SM_RMJH  2816              // 64 u
#define SM_SSUM  3072              // 8 f
#define SM_OPS   4096              // 64KB operand region, 1024-aligned
#define SMEM_TOTAL (SM_OPS + 64 * 1024)

// phase1 (all prefetched, hi only): A [0,32K) (c0,c1); B1 [32K,48K); B2 [48K,64K)
// phase2 (off-diag): p2bi (32K) reloaded into the A region; B1 region reused as B.
#define P1_AH  0
#define P1_B1H (32 * 1024)
#define P1_B2H (48 * 1024)

__device__ float g_n1[MAXN], g_n2[MAXN], g_C[MAXN];
__device__ unsigned int g_rowmax[MAXN];      // zero at load; finalizer re-zeros
__device__ float g_partial[2 * MAXPAIR];
__device__ unsigned int g_work;              // work ticket; finalizer re-zeros
__device__ unsigned int g_done;              // CTA done counter; finalizer re-zeros

// pre-swizzled fp16 hi images: [tile][chunk][16KB]
__device__ __align__(16) unsigned char g_img_p1h[MAXT * 2 * CT];
__device__ __align__(16) unsigned char g_img_p2h[MAXT * 2 * CT];

__device__ __forceinline__ uint32_t smem_u32(const void* p) {
    uint32_t a;
    asm("{ .reg .u64 t; cvta.to.shared.u64 t, %1; cvt.u32.u64 %0, t; }" : "=r"(a) : "l"(p));
    return a;
}
__device__ __forceinline__ int swz(int row, int kc) {
    int b = row * 128 + kc * 2;
    return b ^ ((b >> 3) & 0x70);
}
__device__ __forceinline__ uint32_t taddrA(uint32_t base0, int row, int kcol) {
    return base0 + ((kcol >> 6) << 14) + swz(row, kcol & 63);
}
__device__ __forceinline__ void ldsm4(uint32_t addr, uint32_t r[4]) {
    asm volatile("ldmatrix.sync.aligned.m8n8.x4.shared.b16 {%0,%1,%2,%3}, [%4];"
                 : "=r"(r[0]), "=r"(r[1]), "=r"(r[2]), "=r"(r[3]) : "r"(addr));
}
__device__ __forceinline__ void cp16(uint32_t saddr, const void* g) {
    asm volatile("cp.async.cg.shared.global [%0], [%1], 16;" :: "r"(saddr), "l"(g));
}
#define CP_COMMIT() asm volatile("cp.async.commit_group;" ::: "memory")
#define CP_WAIT0()  asm volatile("cp.async.wait_group 0;" ::: "memory")
#define CP_WAIT1()  asm volatile("cp.async.wait_group 1;" ::: "memory")

#define MMA(d, a, b)                                                               \
    asm volatile("mma.sync.aligned.m16n8k16.row.col.f32.f16.f16.f32 "              \
                 "{%0,%1,%2,%3},{%4,%5,%6,%7},{%8,%9},{%0,%1,%2,%3};"              \
                 : "+f"((d)[0]), "+f"((d)[1]), "+f"((d)[2]), "+f"((d)[3])          \
                 : "r"((a)[0]), "r"((a)[1]), "r"((a)[2]), "r"((a)[3]),             \
                   "r"((b)[0]), "r"((b)[1]))

union HU { __half2 h; uint32_t u; };

__device__ __forceinline__ void cpa(uint32_t sdst, const unsigned char* gsrc, int bytes, int tid) {
    for (int t = tid * 16; t < bytes; t += 4096) cp16(sdst + t, gsrc + t);
}

__device__ __forceinline__ void decode(int w, int nt, int& bi, int& bj, int& h) {
    int pairid = w >> 1;
    h = w & 1;
    bi = 0;
    int rem = pairid;
    while (rem >= nt - bi) { rem -= (nt - bi); bi++; }
    bj = bi + rem;
}

// phase1 prologue: g0 = A both chunks + B1 both chunks (48K); g1 = B2 both chunks (16K)
__device__ __forceinline__ void load_item(uint32_t OPS, int bi, int bj, int h, int tid) {
    size_t b0 = (size_t)(bj * 2 + 0) * CT + h * 8192;
    size_t b1 = (size_t)(bj * 2 + 1) * CT + h * 8192;
    cpa(OPS + P1_AH, g_img_p1h + (size_t)(bi * 2) * CT, 2 * CT, tid);
    cpa(OPS + P1_B1H,        g_img_p1h + b0, 8192, tid);
    cpa(OPS + P1_B1H + 8192, g_img_p1h + b1, 8192, tid);
    CP_COMMIT();                                                   // g0
    cpa(OPS + P1_B2H,        g_img_p2h + b0, 8192, tid);
    cpa(OPS + P1_B2H + 8192, g_img_p2h + b1, 8192, tid);
    CP_COMMIT();                                                   // g1
}

// 4 ksteps of one gram, hi-only: 4 ldsm.x4 -> 8 MMA per kstep
__device__ __forceinline__ void group4(
    uint32_t AH, uint32_t BH, int kAbase,
    int arow, int akoff, int brow, int bkoff, float (&acc)[2][4][4])
{
#pragma unroll
    for (int ks = 0; ks < 4; ks++) {
        const int kA = kAbase + ks * 16;
        const int kB = ks * 16;
        uint32_t ah[2][4];
#pragma unroll
        for (int mf = 0; mf < 2; mf++)
            ldsm4(taddrA(AH, arow + mf * 16, kA + akoff), ah[mf]);
        uint32_t bh[4][2];
#pragma unroll
        for (int np = 0; np < 2; np++) {
            uint32_t t4[4];
            ldsm4(BH + swz(brow + np * 16, kB + bkoff), t4);
            bh[2*np][0]=t4[0]; bh[2*np][1]=t4[1]; bh[2*np+1][0]=t4[2]; bh[2*np+1][1]=t4[3];
        }
#pragma unroll
        for (int mf = 0; mf < 2; mf++)
#pragma unroll
            for (int nf = 0; nf < 4; nf++)
                MMA(acc[mf][nf], ah[mf], bh[nf]);
    }
}

// rows anchored; DZ = diagonal-zeroing compile-time specialized
template<bool DZ>
__device__ __forceinline__ void epi_normal(
    float (&acc)[2][4][4], const float* Crow, const float* ncol,
    int wm, int wn, int qr, int qc, int l, int rbase, int cbase,
    unsigned int* srm, float& sum)
{
    float Cr[2][2], nc[4][2];
#pragma unroll
    for (int mf = 0; mf < 2; mf++) {
        int r0 = wm * 32 + mf * 16 + qr;
        Cr[mf][0] = Crow[r0]; Cr[mf][1] = Crow[r0 + 8];
    }
#pragma unroll
    for (int nf = 0; nf < 4; nf++) {
        int c0 = wn * 32 + nf * 8 + qc;
        nc[nf][0] = ncol[c0]; nc[nf][1] = ncol[c0 + 1];
    }
    float s0 = 0.f, s1 = 0.f;                       // ILP: two partial sums
    float rmax[2][2] = {{0.f, 0.f}, {0.f, 0.f}};
#pragma unroll
    for (int mf = 0; mf < 2; mf++)
#pragma unroll
        for (int nf = 0; nf < 4; nf++)
#pragma unroll
            for (int e = 0; e < 4; e++) {
                int rr = e >> 1, cc = e & 1;
                float v = fmaxf(Cr[mf][rr] - nc[nf][cc] + 2.f * acc[mf][nf][e], 0.f);
                if (DZ) {
                    int rl = rbase + wm * 32 + mf * 16 + qr + rr * 8;
                    int cl = cbase + wn * 32 + nf * 8 + qc + cc;
                    if (rl == cl) v = 0.f;
                }
                if (e & 1) s1 += v; else s0 += v;
                rmax[mf][rr] = fmaxf(rmax[mf][rr], v);
            }
    sum += s0 + s1;
#pragma unroll
    for (int m = 1; m <= 2; m <<= 1)
#pragma unroll
        for (int mf = 0; mf < 2; mf++) {
            rmax[mf][0] = fmaxf(rmax[mf][0], __shfl_xor_sync(0xffffffffu, rmax[mf][0], m));
            rmax[mf][1] = fmaxf(rmax[mf][1], __shfl_xor_sync(0xffffffffu, rmax[mf][1], m));
        }
    if ((l & 3) == 0) {
#pragma unroll
        for (int mf = 0; mf < 2; mf++) {
            atomicMax(&srm[wm * 32 + mf * 16 + qr],     __float_as_uint(rmax[mf][0]));
            atomicMax(&srm[wm * 32 + mf * 16 + qr + 8], __float_as_uint(rmax[mf][1]));
        }
    }
}

// cols anchored (never diagonal)
__device__ __forceinline__ void epi_trans(
    float (&acc)[2][4][4], const float* Ccol, const float* nrow,
    int wm, int wn, int qr, int qc, int l,
    unsigned int* srm, float& sum)
{
    float Ct[4][2], nr[2][2];
#pragma unroll
    for (int nf = 0; nf < 4; nf++) {
        int c0 = wn * 32 + nf * 8 + qc;
        Ct[nf][0] = Ccol[c0]; Ct[nf][1] = Ccol[c0 + 1];
    }
#pragma unroll
    for (int mf = 0; mf < 2; mf++) {
        int r0 = wm * 32 + mf * 16 + qr;
        nr[mf][0] = nrow[r0]; nr[mf][1] = nrow[r0 + 8];
    }
    float s0 = 0.f, s1 = 0.f;
    float cmax[4][2] = {{0.f,0.f},{0.f,0.f},{0.f,0.f},{0.f,0.f}};
#pragma unroll
    for (int mf = 0; mf < 2; mf++)
#pragma unroll
        for (int nf = 0; nf < 4; nf++)
#pragma unroll
            for (int e = 0; e < 4; e++) {
                int rr = e >> 1, cc = e & 1;
                float v = fmaxf(Ct[nf][cc] - nr[mf][rr] + 2.f * acc[mf][nf][e], 0.f);
                if (e & 1) s1 += v; else s0 += v;
                cmax[nf][cc] = fmaxf(cmax[nf][cc], v);
            }
    sum += s0 + s1;
#pragma unroll
    for (int m = 4; m <= 16; m <<= 1)
#pragma unroll
        for (int nf = 0; nf < 4; nf++) {
            cmax[nf][0] = fmaxf(cmax[nf][0], __shfl_xor_sync(0xffffffffu, cmax[nf][0], m));
            cmax[nf][1] = fmaxf(cmax[nf][1], __shfl_xor_sync(0xffffffffu, cmax[nf][1], m));
        }
    if (l < 4) {
#pragma unroll
        for (int nf = 0; nf < 4; nf++) {
            int c0 = wn * 32 + nf * 8 + qc;
            atomicMax(&srm[c0],     __float_as_uint(cmax[nf][0]));
            atomicMax(&srm[c0 + 1], __float_as_uint(cmax[nf][1]));
        }
    }
}

// ---- prep: norms/C + pre-swizzled fp16 hi images ----
__global__ void __launch_bounds__(256)
prep_kernel(const float* __restrict__ p1, const float* __restrict__ p2, int n) {
    int row = blockIdx.x * 8 + (threadIdx.x >> 5);
    int lane = threadIdx.x & 31;
    if (row >= n) return;
    float4 a = ((const float4*)(p1 + (size_t)row * DIM))[lane];
    float4 b = ((const float4*)(p2 + (size_t)row * DIM))[lane];

    float n1 = a.x*a.x + a.y*a.y + a.z*a.z + a.w*a.w;
    float n2 = b.x*b.x + b.y*b.y + b.z*b.z + b.w*b.w;
    float dx = a.x-b.x, dy = a.y-b.y, dz = a.z-b.z, dw = a.w-b.w;
    float dap = dx*dx + dy*dy + dz*dz + dw*dw;
#pragma unroll
    for (int m = 16; m; m >>= 1) {
        n1 += __shfl_xor_sync(0xffffffffu, n1, m);
        n2 += __shfl_xor_sync(0xffffffffu, n2, m);
        dap += __shfl_xor_sync(0xffffffffu, dap, m);
    }
    if (lane == 0) {
        g_n1[row] = n1; g_n2[row] = n2; g_C[row] = dap - n1 + MARGIN;
    }

    int tile = row >> 7, lr = row & 127;
    int c4 = lane * 4, chunk = c4 >> 6, lc = c4 & 63;
    size_t off = (size_t)(tile * 2 + chunk) * CT + swz(lr, lc);

    HU h0, h1;
    h0.h = __floats2half2_rn(a.x, a.y);
    h1.h = __floats2half2_rn(a.z, a.w);
    *(uint2*)(g_img_p1h + off) = make_uint2(h0.u, h1.u);
    h0.h = __floats2half2_rn(b.x, b.y);
    h1.h = __floats2half2_rn(b.z, b.w);
    *(uint2*)(g_img_p2h + off) = make_uint2(h0.u, h1.u);
}

// ---- main: persistent CTAs @3/SM, transposed phase2 reusing resident B1 ----
__global__ void __launch_bounds__(256, 3)
triplet_persist_kernel(float* __restrict__ out, int n, int nt, int nwork) {
    extern __shared__ char smem[];
    const uint32_t sbase = smem_u32(smem);
    const int tid = threadIdx.x;
    const int wid = tid >> 5;
    const int l   = tid & 31;

    float* sCbi   = (float*)(smem + SM_CBI);
    float* sn1bi  = (float*)(smem + SM_N1BI);
    float* sn2bi  = (float*)(smem + SM_N2BI);
    float* sCbjH  = (float*)(smem + SM_CBJH);
    float* sn1bjH = (float*)(smem + SM_N1BJH);
    float* sn2bjH = (float*)(smem + SM_N2BJH);
    unsigned int* srm_bi  = (unsigned int*)(smem + SM_RMI);
    unsigned int* srm_bjH = (unsigned int*)(smem + SM_RMJH);
    float* ssum = (float*)(smem + SM_SSUM);
    const uint32_t OPS = sbase + SM_OPS;

    __shared__ int s_w;

    const int wm = wid & 3;
    const int wn = wid >> 2;
    const int qr = l >> 2;
    const int qc = (l & 3) * 2;
    const int arow = wm * 32 + (l & 7) + ((l >> 3) & 1) * 8;
    const int akoff = (l >> 4) * 8;
    const int brow = wn * 32 + (l & 7) + ((l >> 4) << 3);
    const int bkoff = ((l >> 3) & 1) * 8;

    if (tid == 0) s_w = (int)atomicAdd(&g_work, 1u);
    __syncthreads();
    int w = s_w;
    if (w < nwork) {
        int bi, bj, h; decode(w, nt, bi, bj, h);
        load_item(OPS, bi, bj, h, tid);                 // g0, g1 outstanding
    }

    while (w < nwork) {
        int bi, bj, h; decode(w, nt, bi, bj, h);
        const bool diag = (bi == bj);

        __syncthreads();
        if (tid < 128) {
            srm_bi[tid] = 0u;
            sCbi[tid]  = g_C[bi * TILE + tid];
            sn1bi[tid] = g_n1[bi * TILE + tid];
            sn2bi[tid] = g_n2[bi * TILE + tid];
        } else if (tid < 192) {
            int t = tid - 128;
            srm_bjH[t] = 0u;
            sCbjH[t]  = g_C[bj * TILE + h * 64 + t];
            sn1bjH[t] = g_n1[bj * TILE + h * 64 + t];
            sn2bjH[t] = g_n2[bj * TILE + h * 64 + t];
        } else if (tid == 255) {
            s_w = (int)atomicAdd(&g_work, 1u);          // ticket for NEXT item
        }

        float sum = 0.f;

        CP_WAIT1();             // g0 (A + B1) ready
        __syncthreads();        // publishes s_w too
        const int wn_next = s_w;

        // ---- acc1 = p1bi . p1bjH^T over full K; epilogue covers B2 flight ----
        {
            float acc[2][4][4];
#pragma unroll
            for (int mf = 0; mf < 2; mf++)
#pragma unroll
                for (int nf = 0; nf < 4; nf++)
#pragma unroll
                    for (int e = 0; e < 4; e++) acc[mf][nf][e] = 0.f;
            group4(OPS + P1_AH, OPS + P1_B1H,        0,  arow, akoff, brow, bkoff, acc);
            group4(OPS + P1_AH, OPS + P1_B1H + 8192, 64, arow, akoff, brow, bkoff, acc);
            if (diag) {
                epi_normal<true>(acc, sCbi, sn1bjH, wm, wn, qr, qc, l,
                                 bi * TILE, bj * TILE + h * 64, srm_bi, sum);
            } else {
                epi_normal<false>(acc, sCbi, sn1bjH, wm, wn, qr, qc, l,
                                  0, 0, srm_bi, sum);
                epi_trans(acc, sCbjH, sn1bi, wm, wn, qr, qc, l, srm_bjH, sum);
            }
        }

        CP_WAIT0();             // g1 (B2) ready
        __syncthreads();

        // ---- acc2 = p1bi . p2bjH^T over full K ----
        {
            float acc[2][4][4];
#pragma unroll
            for (int mf = 0; mf < 2; mf++)
#pragma unroll
                for (int nf = 0; nf < 4; nf++)
#pragma unroll
                    for (int e = 0; e < 4; e++) acc[mf][nf][e] = 0.f;
            group4(OPS + P1_AH, OPS + P1_B2H,        0,  arow, akoff, brow, bkoff, acc);
            group4(OPS + P1_AH, OPS + P1_B2H + 8192, 64, arow, akoff, brow, bkoff, acc);
            __syncthreads();    // A-region reads done (B1 stays resident)

            if (diag) {
                if (wn_next < nwork) {
                    int nbi, nbj, nh; decode(wn_next, nt, nbi, nbj, nh);
                    load_item(OPS, nbi, nbj, nh, tid);
                }
                epi_normal<true>(acc, sCbi, sn2bjH, wm, wn, qr, qc, l,
                                 bi * TILE, bj * TILE + h * 64, srm_bi, sum);
            } else {
                // phase2 operand: p2bi (both chunks) into the freed A region
                cpa(OPS + P1_AH, g_img_p2h + (size_t)(bi * 2) * CT, 2 * CT, tid);
                CP_COMMIT();
                epi_normal<false>(acc, sCbi, sn2bjH, wm, wn, qr, qc, l,
                                  0, 0, srm_bi, sum);
            }
        }

        // ---- phase2 (off-diag): G2b^T = p2bi . p1bjH^T (B1 region reused) ----
        if (!diag) {
            float acc[2][4][4];
#pragma unroll
            for (int mf = 0; mf < 2; mf++)
#pragma unroll
                for (int nf = 0; nf < 4; nf++)
#pragma unroll
                    for (int e = 0; e < 4; e++) acc[mf][nf][e] = 0.f;

            CP_WAIT0();         // p2bi ready
            __syncthreads();
            group4(OPS + P1_AH, OPS + P1_B1H,        0,  arow, akoff, brow, bkoff, acc);
            group4(OPS + P1_AH, OPS + P1_B1H + 8192, 64, arow, akoff, brow, bkoff, acc);
            __syncthreads();    // all phase2 operand reads done

            if (wn_next < nwork) {
                int nbi, nbj, nh; decode(wn_next, nt, nbi, nbj, nh);
                load_item(OPS, nbi, nbj, nh, tid);
            }
            epi_trans(acc, sCbjH, sn2bi, wm, wn, qr, qc, l, srm_bjH, sum);
        }

        // ---- publish this item ----
#pragma unroll
        for (int m = 16; m; m >>= 1) sum += __shfl_xor_sync(0xffffffffu, sum, m);
        if (l == 0) ssum[wid] = sum;
        __syncthreads();
        if (tid < 128)
            atomicMax(&g_rowmax[bi * TILE + tid], srm_bi[tid]);
        else if (tid < 192)
            atomicMax(&g_rowmax[bj * TILE + h * 64 + (tid - 128)], srm_bjH[tid - 128]);
        if (tid == 0) {
            float t = 0.f;
#pragma unroll
            for (int ww = 0; ww < 8; ww++) t += ssum[ww];
            g_partial[w] = t;
        }
        w = wn_next;
    }

    // ---- CTA done; last CTA finalizes ----
    __threadfence();
    __shared__ unsigned int s_last;
    if (tid == 0) s_last = (atomicAdd(&g_done, 1u) == (unsigned)(gridDim.x - 1)) ? 1u : 0u;
    __syncthreads();
    if (!s_last) return;
    __threadfence();

    double smax = 0.0, ssumd = 0.0;
    for (int i = tid; i < n; i += 256) {
        smax += (double)__uint_as_float(g_rowmax[i]);
        g_rowmax[i] = 0u;
    }
    for (int i = tid; i < nwork; i += 256) ssumd += (double)g_partial[i];
#pragma unroll
    for (int m = 16; m; m >>= 1) {
        smax  += __shfl_xor_sync(0xffffffffu, smax, m);
        ssumd += __shfl_xor_sync(0xffffffffu, ssumd, m);
    }
    __shared__ double d1[8], d2[8];
    if (l == 0) { d1[wid] = smax; d2[wid] = ssumd; }
    __syncthreads();
    if (tid == 0) {
        double t1 = 0.0, t2 = 0.0;
#pragma unroll
        for (int ww = 0; ww < 8; ww++) { t1 += d1[ww]; t2 += d2[ww]; }
        out[0] = (float)(t1 / (double)n);
        out[1] = (float)(t2 / (2.0 * (double)n * (double)(n - 1)));
        g_work = 0u;
        g_done = 0u;
    }
}

extern "C" void kernel_launch(void* const* d_in, const int* in_sizes, int n_in,
                              void* d_out, int out_size) {
    const float* p1 = (const float*)d_in[0];
    const float* p2 = (const float*)d_in[1];
    float* out = (float*)d_out;
    const int n = in_sizes[0] / DIM;            // 4096
    const int nt = n / TILE;                    // 32
    const int nwork = nt * (nt + 1);            // 1056 half-pairs

    int nsm = 148;
    cudaDeviceGetAttribute(&nsm, cudaDevAttrMultiProcessorCount, 0);

    cudaFuncSetAttribute(triplet_persist_kernel,
                         cudaFuncAttributeMaxDynamicSharedMemorySize, SMEM_TOTAL);

    prep_kernel<<<n / 8, 256>>>(p1, p2, n);
    triplet_persist_kernel<<<nsm * 3, 256, SMEM_TOTAL>>>(out, n, nt, nwork);
}